// round 12
// baseline (speedup 1.0000x reference)
#include <cuda_runtime.h>
#include <float.h>

// Fused sRGB->CIELab + per-image L min-max normalization, single kernel with
// cross-CTA per-image sync. 8 CTAs per image.
//   phase1 (pre-sync): read own 2048 px ONCE, gamma (6 MUFU/px) + 3x3 matrix,
//          stash X,Y,Z planes in smem, minmax on Y (free — it's a plane),
//          publish partial.
//   spin  : thread0 acquire-spins until all 8 partials landed.
//   phase2 (post-sync, SHORT): 3 cbrt (MUFU) + finals + coalesced writes.
// All transcendentals on MUFU (R11 proved FMA-Newton cbrt is slower).
// Self-resetting counters, no memset node. DRAM = 1 read + 1 write.

#define NPIX    16384
#define NIMG    512
#define SUBS    8
#define THREADS 256
#define PX_CTA  (NPIX / SUBS)          // 2048
#define NG_CTA  (PX_CTA / 4)           // 512
#define GROUPS  (NG_CTA / THREADS)     // 2

__device__ float g_pmin[NIMG * SUBS];
__device__ float g_pmax[NIMG * SUBS];
__device__ int   g_arrive[NIMG];       // zero-init; self-reset each launch
__device__ int   g_done[NIMG];         // zero-init; self-reset each launch

__device__ __forceinline__ float mufu_lg2(float x) {
    float r; asm("lg2.approx.f32 %0, %1;" : "=f"(r) : "f"(x)); return r;
}
__device__ __forceinline__ float mufu_ex2(float x) {
    float r; asm("ex2.approx.f32 %0, %1;" : "=f"(r) : "f"(x)); return r;
}
__device__ __forceinline__ float mufu_rcp(float x) {
    float r; asm("rcp.approx.f32 %0, %1;" : "=f"(r) : "f"(x)); return r;
}

__device__ __forceinline__ float srgb_lin(float c) {
    float t = fmaf(c, 1.0f / 1.055f, 0.055f / 1.055f);
    float p = mufu_ex2(2.4f * mufu_lg2(t));
    return (c > 0.04045f) ? p : c * (1.0f / 12.92f);
}

__device__ __forceinline__ float xyz_f(float t) {
    float cr = mufu_ex2((1.0f / 3.0f) * mufu_lg2(t));
    return (t > 0.008856f) ? cr : fmaf(t, 7.787f, 16.0f / 116.0f);
}

__global__ void __launch_bounds__(THREADS, 8)
rgb2lab_sync_kernel(const float* __restrict__ x, float* __restrict__ out) {
    __shared__ float4 sX[NG_CTA];      // 8KB X plane (4 px per float4)
    __shared__ float4 sY[NG_CTA];      // 8KB Y plane
    __shared__ float4 sZ[NG_CTA];      // 8KB Z plane
    __shared__ float  red[18];

    const int bid = blockIdx.x;
    const int img = bid >> 3;
    const int tid = threadIdx.x;

    const float4* in4 = (const float4*)x   + bid * (PX_CTA * 3 / 4);
    float4*       o4  = (float4*)      out + bid * (PX_CTA * 3 / 4);

    float ymin = FLT_MAX, ymax = -FLT_MAX;

    const float M00 = 0.412453f / 0.95047f, M01 = 0.357580f / 0.95047f, M02 = 0.180423f / 0.95047f;
    const float M10 = 0.212671f,            M11 = 0.715160f,            M12 = 0.072169f;
    const float M20 = 0.019334f / 1.08883f, M21 = 0.119193f / 1.08883f, M22 = 0.950227f / 1.08883f;

    // -------- phase 1: read once, gamma + matrix, stash XYZ, minmax Y -----
    #pragma unroll
    for (int j = 0; j < GROUPS; j++) {
        int gi = tid + j * THREADS;
        float4 v0 = __ldcs(&in4[gi * 3 + 0]);
        float4 v1 = __ldcs(&in4[gi * 3 + 1]);
        float4 v2 = __ldcs(&in4[gi * 3 + 2]);

        float4 r4 = make_float4(srgb_lin(v0.x), srgb_lin(v0.w), srgb_lin(v1.z), srgb_lin(v2.y));
        float4 g4 = make_float4(srgb_lin(v0.y), srgb_lin(v1.x), srgb_lin(v1.w), srgb_lin(v2.z));
        float4 b4 = make_float4(srgb_lin(v0.z), srgb_lin(v1.y), srgb_lin(v2.x), srgb_lin(v2.w));

        float4 X4, Y4, Z4;
        X4.x = fmaf(M00, r4.x, fmaf(M01, g4.x, M02 * b4.x));
        X4.y = fmaf(M00, r4.y, fmaf(M01, g4.y, M02 * b4.y));
        X4.z = fmaf(M00, r4.z, fmaf(M01, g4.z, M02 * b4.z));
        X4.w = fmaf(M00, r4.w, fmaf(M01, g4.w, M02 * b4.w));
        Y4.x = fmaf(M10, r4.x, fmaf(M11, g4.x, M12 * b4.x));
        Y4.y = fmaf(M10, r4.y, fmaf(M11, g4.y, M12 * b4.y));
        Y4.z = fmaf(M10, r4.z, fmaf(M11, g4.z, M12 * b4.z));
        Y4.w = fmaf(M10, r4.w, fmaf(M11, g4.w, M12 * b4.w));
        Z4.x = fmaf(M20, r4.x, fmaf(M21, g4.x, M22 * b4.x));
        Z4.y = fmaf(M20, r4.y, fmaf(M21, g4.y, M22 * b4.y));
        Z4.z = fmaf(M20, r4.z, fmaf(M21, g4.z, M22 * b4.z));
        Z4.w = fmaf(M20, r4.w, fmaf(M21, g4.w, M22 * b4.w));

        sX[gi] = X4;  sY[gi] = Y4;  sZ[gi] = Z4;

        ymin = fminf(fminf(fminf(ymin, Y4.x), fminf(Y4.y, Y4.z)), Y4.w);
        ymax = fmaxf(fmaxf(fmaxf(ymax, Y4.x), fmaxf(Y4.y, Y4.z)), Y4.w);
    }

    // ---------------- CTA-local reduce ------------------------------------
    #pragma unroll
    for (int off = 16; off > 0; off >>= 1) {
        ymin = fminf(ymin, __shfl_xor_sync(0xffffffffu, ymin, off));
        ymax = fmaxf(ymax, __shfl_xor_sync(0xffffffffu, ymax, off));
    }
    int lane = tid & 31, wid = tid >> 5;
    if (lane == 0) { red[wid] = ymin; red[8 + wid] = ymax; }
    __syncthreads();

    // ---------------- publish + spin + self-reset -------------------------
    if (tid == 0) {
        float mn = red[0], mx = red[8];
        #pragma unroll
        for (int i = 1; i < 8; i++) {
            mn = fminf(mn, red[i]);
            mx = fmaxf(mx, red[8 + i]);
        }
        g_pmin[bid] = mn;
        g_pmax[bid] = mx;
        asm volatile("red.release.gpu.global.add.s32 [%0], 1;"
                     :: "l"(&g_arrive[img]) : "memory");

        int c;
        do {
            asm volatile("ld.acquire.gpu.global.s32 %0, [%1];"
                         : "=r"(c) : "l"(&g_arrive[img]) : "memory");
            if (c < SUBS) __nanosleep(64);
        } while (c < SUBS);

        float fm = FLT_MAX, fM = -FLT_MAX;
        #pragma unroll
        for (int i = 0; i < SUBS; i++) {
            fm = fminf(fm, g_pmin[img * 8 + i]);
            fM = fmaxf(fM, g_pmax[img * 8 + i]);
        }
        float fmn = xyz_f(fm);                 // same f as per-pixel path
        float sfv = mufu_rcp(xyz_f(fM) - fmn);
        red[16] = sfv;
        red[17] = -fmn * sfv;                  // nsf: L = fma(fy, sf, nsf)

        int prev = atomicAdd(&g_done[img], 1);
        if (prev == SUBS - 1) {
            g_arrive[img] = 0;
            g_done[img]   = 0;
        }
    }
    __syncthreads();
    const float sf  = red[16];
    const float nsf = red[17];

    // -------- phase 2 (SHORT): 3 cbrt + finals + write ---------------------
    #pragma unroll
    for (int j = 0; j < GROUPS; j++) {
        int gi = tid + j * THREADS;
        float4 X4 = sX[gi];
        float4 Y4 = sY[gi];
        float4 Z4 = sZ[gi];

        float L[4], A[4], B[4];
        const float* XX = &X4.x; const float* YY = &Y4.x; const float* ZZ = &Z4.x;
        #pragma unroll
        for (int p = 0; p < 4; p++) {
            float fx = xyz_f(XX[p]);
            float fy = xyz_f(YY[p]);
            float fz = xyz_f(ZZ[p]);
            L[p] = fmaf(fy, sf, nsf);
            A[p] = fmaf(fx - fy, 500.0f / 255.0f, 128.0f / 255.0f);
            B[p] = fmaf(fy - fz, 200.0f / 255.0f, 128.0f / 255.0f);
        }

        o4[gi * 3 + 0] = make_float4(L[0], A[0], B[0], L[1]);
        o4[gi * 3 + 1] = make_float4(A[1], B[1], L[2], A[2]);
        o4[gi * 3 + 2] = make_float4(B[2], L[3], A[3], B[3]);
    }
}

extern "C" void kernel_launch(void* const* d_in, const int* in_sizes, int n_in,
                              void* d_out, int out_size) {
    const float* x   = (const float*)d_in[0];
    float*       out = (float*)d_out;

    rgb2lab_sync_kernel<<<NIMG * SUBS, THREADS>>>(x, out);
}

// round 13
// speedup vs baseline: 1.3484x; 1.3484x over previous
#include <cuda_runtime.h>
#include <float.h>

// Fused sRGB->CIELab + per-image L min-max normalization. Two-kernel (R3 base,
// best measured) + f32x2 packed FMA math (sm_103a): half the issue slots for
// all non-MUFU arithmetic, identical fp32 results per lane.
// K1: per-image Y min/max (L monotonic in Y), 4 CTAs/image.
// K2: full Lab + normalize, 8 CTAs/image, reverse image order (L2 reuse),
//     streaming float4 stores.

#define NPIX      16384
#define NIMG      512
#define K1_SUBS   4
#define K2_SUBS   8
#define THREADS   256
#define K1_PX     (NPIX / K1_SUBS)         // 4096
#define K2_PX     (NPIX / K2_SUBS)         // 2048
#define K1_GROUPS (K1_PX / (THREADS * 4))  // 4
#define K2_GROUPS (K2_PX / (THREADS * 4))  // 2

typedef unsigned long long u64;

__device__ float g_pmin[NIMG * K1_SUBS];
__device__ float g_pmax[NIMG * K1_SUBS];

// ---------------- f32x2 packed helpers ----------------
__device__ __forceinline__ u64 pk2(float lo, float hi) {
    u64 d; asm("mov.b64 %0, {%1, %2};" : "=l"(d) : "f"(lo), "f"(hi)); return d;
}
__device__ __forceinline__ void upk2(u64 d, float& lo, float& hi) {
    asm("mov.b64 {%0, %1}, %2;" : "=f"(lo), "=f"(hi) : "l"(d));
}
__device__ __forceinline__ u64 fma2(u64 a, u64 b, u64 c) {
    u64 d; asm("fma.rn.f32x2 %0, %1, %2, %3;" : "=l"(d) : "l"(a), "l"(b), "l"(c)); return d;
}
__device__ __forceinline__ u64 mul2(u64 a, u64 b) {
    u64 d; asm("mul.rn.f32x2 %0, %1, %2;" : "=l"(d) : "l"(a), "l"(b)); return d;
}

__device__ __forceinline__ float mufu_lg2(float x) {
    float r; asm("lg2.approx.f32 %0, %1;" : "=f"(r) : "f"(x)); return r;
}
__device__ __forceinline__ float mufu_ex2(float x) {
    float r; asm("ex2.approx.f32 %0, %1;" : "=f"(r) : "f"(x)); return r;
}
__device__ __forceinline__ float mufu_rcp(float x) {
    float r; asm("rcp.approx.f32 %0, %1;" : "=f"(r) : "f"(x)); return r;
}

// packed sRGB->linear for a pixel pair (one channel)
__device__ __forceinline__ u64 srgb_lin2(u64 c2) {
    const u64 CA  = pk2(1.0f / 1.055f, 1.0f / 1.055f);
    const u64 CB  = pk2(0.055f / 1.055f, 0.055f / 1.055f);
    const u64 C24 = pk2(2.4f, 2.4f);
    const u64 CI  = pk2(1.0f / 12.92f, 1.0f / 12.92f);
    u64 t2 = fma2(c2, CA, CB);
    float t0, t1;  upk2(t2, t0, t1);
    u64 m2 = mul2(pk2(mufu_lg2(t0), mufu_lg2(t1)), C24);
    float m0, m1;  upk2(m2, m0, m1);
    float p0 = mufu_ex2(m0), p1 = mufu_ex2(m1);
    u64 w2 = mul2(c2, CI);
    float c0, c1;  upk2(c2, c0, c1);
    float w0, w1;  upk2(w2, w0, w1);
    float r0 = (c0 > 0.04045f) ? p0 : w0;
    float r1 = (c1 > 0.04045f) ? p1 : w1;
    return pk2(r0, r1);
}

// packed Lab f() for a pixel pair
__device__ __forceinline__ u64 xyz_f2(u64 t2) {
    const u64 C13 = pk2(1.0f / 3.0f, 1.0f / 3.0f);
    const u64 C77 = pk2(7.787f, 7.787f);
    const u64 C16 = pk2(16.0f / 116.0f, 16.0f / 116.0f);
    float t0, t1;  upk2(t2, t0, t1);
    u64 m2 = mul2(pk2(mufu_lg2(t0), mufu_lg2(t1)), C13);
    float m0, m1;  upk2(m2, m0, m1);
    float e0 = mufu_ex2(m0), e1 = mufu_ex2(m1);
    u64 w2 = fma2(t2, C77, C16);
    float w0, w1;  upk2(w2, w0, w1);
    float r0 = (t0 > 0.008856f) ? e0 : w0;
    float r1 = (t1 > 0.008856f) ? e1 : w1;
    return pk2(r0, r1);
}

// scalar f() for the reduction endpoints (same math as packed path)
__device__ __forceinline__ float xyz_f(float t) {
    float cr = mufu_ex2((1.0f / 3.0f) * mufu_lg2(t));
    return (t > 0.008856f) ? cr : fmaf(t, 7.787f, 16.0f / 116.0f);
}

// ---------------------------------------------------------------- K1
__global__ void __launch_bounds__(THREADS)
minmax_kernel(const float* __restrict__ x) {
    __shared__ float red[16];
    const int bid = blockIdx.x;
    const int tid = threadIdx.x;

    const float4* in4 = (const float4*)x + bid * (K1_PX * 3 / 4);

    const u64 MY0 = pk2(0.212671f, 0.212671f);
    const u64 MY1 = pk2(0.715160f, 0.715160f);
    const u64 MY2 = pk2(0.072169f, 0.072169f);

    float ymin = FLT_MAX, ymax = -FLT_MAX;

    #pragma unroll
    for (int j = 0; j < K1_GROUPS; j++) {
        int gi = tid + j * THREADS;
        float4 v0 = in4[gi * 3 + 0];
        float4 v1 = in4[gi * 3 + 1];
        float4 v2 = in4[gi * 3 + 2];

        // pair A = px0,px1 ; pair B = px2,px3
        u64 rA = srgb_lin2(pk2(v0.x, v0.w));
        u64 gA = srgb_lin2(pk2(v0.y, v1.x));
        u64 bA = srgb_lin2(pk2(v0.z, v1.y));
        u64 rB = srgb_lin2(pk2(v1.z, v2.y));
        u64 gB = srgb_lin2(pk2(v1.w, v2.z));
        u64 bB = srgb_lin2(pk2(v2.x, v2.w));

        u64 yA = fma2(rA, MY0, fma2(gA, MY1, mul2(bA, MY2)));
        u64 yB = fma2(rB, MY0, fma2(gB, MY1, mul2(bB, MY2)));

        float y0, y1, y2, y3;
        upk2(yA, y0, y1);  upk2(yB, y2, y3);
        ymin = fminf(fminf(fminf(ymin, y0), fminf(y1, y2)), y3);
        ymax = fmaxf(fmaxf(fmaxf(ymax, y0), fmaxf(y1, y2)), y3);
    }

    #pragma unroll
    for (int off = 16; off > 0; off >>= 1) {
        ymin = fminf(ymin, __shfl_xor_sync(0xffffffffu, ymin, off));
        ymax = fmaxf(ymax, __shfl_xor_sync(0xffffffffu, ymax, off));
    }
    int lane = tid & 31, wid = tid >> 5;
    if (lane == 0) { red[wid] = ymin; red[8 + wid] = ymax; }
    __syncthreads();
    if (tid == 0) {
        float mn = red[0], mx = red[8];
        #pragma unroll
        for (int i = 1; i < 8; i++) {
            mn = fminf(mn, red[i]);
            mx = fmaxf(mx, red[8 + i]);
        }
        g_pmin[bid] = mn;
        g_pmax[bid] = mx;
    }
}

// ---------------------------------------------------------------- K2
__global__ void __launch_bounds__(THREADS)
convert_kernel(const float* __restrict__ x, float* __restrict__ out) {
    const int bid = blockIdx.x;
    const int img = (NIMG - 1) - (bid >> 3);   // reverse order for L2 reuse
    const int sub = bid & 7;
    const int tid = threadIdx.x;

    float ymn = fminf(fminf(g_pmin[img * 4 + 0], g_pmin[img * 4 + 1]),
                      fminf(g_pmin[img * 4 + 2], g_pmin[img * 4 + 3]));
    float ymx = fmaxf(fmaxf(g_pmax[img * 4 + 0], g_pmax[img * 4 + 1]),
                      fmaxf(g_pmax[img * 4 + 2], g_pmax[img * 4 + 3]));
    float fmin = xyz_f(ymn);
    float sf   = mufu_rcp(xyz_f(ymx) - fmin);
    const u64 SF2  = pk2(sf, sf);
    const u64 NSF2 = pk2(-fmin * sf, -fmin * sf);

    const u64 M00 = pk2(0.412453f / 0.95047f, 0.412453f / 0.95047f);
    const u64 M01 = pk2(0.357580f / 0.95047f, 0.357580f / 0.95047f);
    const u64 M02 = pk2(0.180423f / 0.95047f, 0.180423f / 0.95047f);
    const u64 M10 = pk2(0.212671f, 0.212671f);
    const u64 M11 = pk2(0.715160f, 0.715160f);
    const u64 M12 = pk2(0.072169f, 0.072169f);
    const u64 M20 = pk2(0.019334f / 1.08883f, 0.019334f / 1.08883f);
    const u64 M21 = pk2(0.119193f / 1.08883f, 0.119193f / 1.08883f);
    const u64 M22 = pk2(0.950227f / 1.08883f, 0.950227f / 1.08883f);
    const u64 NEG1 = pk2(-1.0f, -1.0f);
    const u64 K5   = pk2(500.0f / 255.0f, 500.0f / 255.0f);
    const u64 K2_  = pk2(200.0f / 255.0f, 200.0f / 255.0f);
    const u64 K128 = pk2(128.0f / 255.0f, 128.0f / 255.0f);

    const int base4 = img * (NPIX * 3 / 4) + sub * (K2_PX * 3 / 4);
    const float4* in4 = (const float4*)x   + base4;
    float4*       o4  = (float4*)      out + base4;

    #pragma unroll
    for (int j = 0; j < K2_GROUPS; j++) {
        int gi = tid + j * THREADS;
        float4 v0 = in4[gi * 3 + 0];
        float4 v1 = in4[gi * 3 + 1];
        float4 v2 = in4[gi * 3 + 2];

        float Lp[4], Ap[4], Bp[4];

        // two pixel pairs: (0,1) and (2,3)
        #pragma unroll
        for (int h = 0; h < 2; h++) {
            u64 c_r = (h == 0) ? pk2(v0.x, v0.w) : pk2(v1.z, v2.y);
            u64 c_g = (h == 0) ? pk2(v0.y, v1.x) : pk2(v1.w, v2.z);
            u64 c_b = (h == 0) ? pk2(v0.z, v1.y) : pk2(v2.x, v2.w);

            u64 r2 = srgb_lin2(c_r);
            u64 g2 = srgb_lin2(c_g);
            u64 b2 = srgb_lin2(c_b);

            u64 X2 = fma2(r2, M00, fma2(g2, M01, mul2(b2, M02)));
            u64 Y2 = fma2(r2, M10, fma2(g2, M11, mul2(b2, M12)));
            u64 Z2 = fma2(r2, M20, fma2(g2, M21, mul2(b2, M22)));

            u64 fx2 = xyz_f2(X2);
            u64 fy2 = xyz_f2(Y2);
            u64 fz2 = xyz_f2(Z2);

            u64 L2v = fma2(fy2, SF2, NSF2);
            u64 dxy = fma2(fy2, NEG1, fx2);            // fx - fy
            u64 A2v = fma2(dxy, K5, K128);
            u64 dyz = fma2(fz2, NEG1, fy2);            // fy - fz
            u64 B2v = fma2(dyz, K2_, K128);

            upk2(L2v, Lp[2 * h], Lp[2 * h + 1]);
            upk2(A2v, Ap[2 * h], Ap[2 * h + 1]);
            upk2(B2v, Bp[2 * h], Bp[2 * h + 1]);
        }

        __stcs(&o4[gi * 3 + 0], make_float4(Lp[0], Ap[0], Bp[0], Lp[1]));
        __stcs(&o4[gi * 3 + 1], make_float4(Ap[1], Bp[1], Lp[2], Ap[2]));
        __stcs(&o4[gi * 3 + 2], make_float4(Bp[2], Lp[3], Ap[3], Bp[3]));
    }
}

extern "C" void kernel_launch(void* const* d_in, const int* in_sizes, int n_in,
                              void* d_out, int out_size) {
    const float* x   = (const float*)d_in[0];
    float*       out = (float*)d_out;

    minmax_kernel <<<NIMG * K1_SUBS, THREADS>>>(x);
    convert_kernel<<<NIMG * K2_SUBS, THREADS>>>(x, out);
}